// round 1
// baseline (speedup 1.0000x reference)
#include <cuda_runtime.h>
#include <cuda_bf16.h>
#include <mma.h>

using namespace nvcuda;

// Problem dims
#define QN 2048
#define SN 8
#define DN 2048
#define SPN 100
#define NCLS 20
#define MROWS (QN * SN)          // 16384
#define NCOLS (SPN * SN)         // 800
#define NPAD 832                 // padded to multiple of 64
#define LBDA 0.1f
#define ILBDA 10.0f

// -------- scratch (device globals; allocation-free kernel_launch) --------
__device__ __nv_bfloat16 g_A[(size_t)MROWS * DN];   // 64 MB
__device__ __nv_bfloat16 g_B[(size_t)NPAD * DN];    // 3.4 MB
__device__ float g_dot[(size_t)MROWS * NPAD];       // 54.5 MB
__device__ float g_tfn[MROWS];
__device__ float g_sfn[NPAD];
__device__ float g_invcnt[NCLS];

// -------- kernel 0: inverse class counts --------
__global__ void k_invcnt(const int* __restrict__ labels) {
    __shared__ int cnt[NCLS];
    if (threadIdx.x < NCLS) cnt[threadIdx.x] = 0;
    __syncthreads();
    for (int i = threadIdx.x; i < SPN; i += blockDim.x)
        atomicAdd(&cnt[labels[i]], 1);
    __syncthreads();
    if (threadIdx.x < NCLS) {
        int c = cnt[threadIdx.x];
        g_invcnt[threadIdx.x] = 1.0f / (float)(c > 0 ? c : 1);
    }
}

// -------- zero output --------
__global__ void k_zero(float* __restrict__ out, int n) {
    int i = blockIdx.x * blockDim.x + threadIdx.x;
    if (i < n) out[i] = 0.0f;
}

// -------- kernel 1: fp32 -> bf16 conversion + row L2 norms --------
// MODE 0: target features -> g_A/g_tfn ; MODE 1: support -> g_B/g_sfn (pad rows zeroed)
template <int MODE>
__global__ void __launch_bounds__(256) k_conv_norm(const float* __restrict__ src) {
    const int C = DN;
    int r = blockIdx.x;
    __nv_bfloat16* dst = (MODE == 0) ? g_A : g_B;
    float* norms = (MODE == 0) ? g_tfn : g_sfn;
    const int valid = (MODE == 0) ? MROWS : NCOLS;

    __nv_bfloat162* drow = reinterpret_cast<__nv_bfloat162*>(dst + (size_t)r * C);
    float ssum = 0.0f;
    if (r < valid) {
        const float4* s = reinterpret_cast<const float4*>(src + (size_t)r * C);
        for (int i = threadIdx.x; i < C / 4; i += blockDim.x) {
            float4 v = s[i];
            ssum = fmaf(v.x, v.x, fmaf(v.y, v.y, fmaf(v.z, v.z, fmaf(v.w, v.w, ssum))));
            drow[2 * i]     = __floats2bfloat162_rn(v.x, v.y);
            drow[2 * i + 1] = __floats2bfloat162_rn(v.z, v.w);
        }
    } else {
        __nv_bfloat162 z = __floats2bfloat162_rn(0.f, 0.f);
        for (int i = threadIdx.x; i < C / 4; i += blockDim.x) {
            drow[2 * i] = z;
            drow[2 * i + 1] = z;
        }
    }
    // block reduce
    #pragma unroll
    for (int o = 16; o; o >>= 1) ssum += __shfl_xor_sync(0xFFFFFFFFu, ssum, o);
    __shared__ float wsum[8];
    int lane = threadIdx.x & 31, wid = threadIdx.x >> 5;
    if (lane == 0) wsum[wid] = ssum;
    __syncthreads();
    if (threadIdx.x == 0) {
        float s = 0.f;
        #pragma unroll
        for (int i = 0; i < 8; i++) s += wsum[i];
        norms[r] = sqrtf(s);
    }
}

// -------- kernel 2: bf16 GEMM (wmma), dot[M, NPAD] = A @ B^T --------
// A row-major [M, K]; B rows are support frames [NPAD, K] -> acts as col-major [K, NPAD]
__global__ void __launch_bounds__(256) k_gemm() {
    const int Kd = DN;
    __shared__ __nv_bfloat16 As[64][40];
    __shared__ __nv_bfloat16 Bs[64][40];

    int bm = blockIdx.y * 64;
    int bn = blockIdx.x * 64;
    int tid = threadIdx.x;
    int warp = tid >> 5;
    int wm = warp >> 1;   // 0..3 (M dir, 16 rows each)
    int wn = warp & 1;    // 0..1 (N dir, 32 cols each)

    wmma::fragment<wmma::accumulator, 16, 16, 16, float> c0, c1;
    wmma::fill_fragment(c0, 0.0f);
    wmma::fill_fragment(c1, 0.0f);

    int lr = tid >> 2;          // 0..63
    int lc = (tid & 3) * 8;     // 0,8,16,24
    const __nv_bfloat16* Aptr = g_A + (size_t)(bm + lr) * Kd + lc;
    const __nv_bfloat16* Bptr = g_B + (size_t)(bn + lr) * Kd + lc;

    for (int k0 = 0; k0 < Kd; k0 += 32) {
        *reinterpret_cast<uint4*>(&As[lr][lc]) = *reinterpret_cast<const uint4*>(Aptr + k0);
        *reinterpret_cast<uint4*>(&Bs[lr][lc]) = *reinterpret_cast<const uint4*>(Bptr + k0);
        __syncthreads();
        #pragma unroll
        for (int kk = 0; kk < 32; kk += 16) {
            wmma::fragment<wmma::matrix_a, 16, 16, 16, __nv_bfloat16, wmma::row_major> af;
            wmma::fragment<wmma::matrix_b, 16, 16, 16, __nv_bfloat16, wmma::col_major> bf0, bf1;
            wmma::load_matrix_sync(af, &As[wm * 16][kk], 40);
            wmma::load_matrix_sync(bf0, &Bs[wn * 32][kk], 40);
            wmma::load_matrix_sync(bf1, &Bs[wn * 32 + 16][kk], 40);
            wmma::mma_sync(c0, af, bf0, c0);
            wmma::mma_sync(c1, af, bf1, c1);
        }
        __syncthreads();
    }

    float* Cp = g_dot + (size_t)(bm + wm * 16) * NPAD + bn + wn * 32;
    wmma::store_matrix_sync(Cp, c0, NPAD, wmma::mem_row_major);
    wmma::store_matrix_sync(Cp + 16, c1, NPAD, wmma::mem_row_major);
}

// -------- OTAM soft-DTW --------
__device__ __forceinline__ float softmin2(float a, float b) {
    float mn = fminf(a, b);
    float df = fabsf(a - b);
    return mn - LBDA * __logf(1.0f + __expf(-df * ILBDA));
}
__device__ __forceinline__ float softmin3(float a, float b, float c) {
    float mn = fminf(a, fminf(b, c));
    float s = __expf((mn - a) * ILBDA) + __expf((mn - b) * ILBDA) + __expf((mn - c) * ILBDA);
    return mn - LBDA * __logf(s);
}

template <bool TR>
__device__ __forceinline__ float otam_dp(const float d[8][8]) {
    // D(i,j) = dist row i (time), col j (support); padded M=10 columns
    float prev[10];
    prev[0] = 0.0f;
    #pragma unroll
    for (int m = 1; m <= 8; m++) {
        float v = TR ? d[m - 1][0] : d[0][m - 1];
        prev[m] = prev[m - 1] + v;
    }
    prev[9] = prev[8];
    #pragma unroll
    for (int i = 1; i < 8; i++) {
        float cur[10];
        cur[0] = 0.0f;
        {
            float v = TR ? d[0][i] : d[i][0];
            cur[1] = v + softmin3(prev[0], prev[1], 0.0f);
        }
        #pragma unroll
        for (int m = 2; m <= 8; m++) {
            float v = TR ? d[m - 1][i] : d[i][m - 1];
            cur[m] = v + softmin2(prev[m - 1], cur[m - 1]);
        }
        cur[9] = softmin3(prev[8], prev[9], cur[8]);
        #pragma unroll
        for (int m = 0; m < 10; m++) prev[m] = cur[m];
    }
    return prev[9];
}

// -------- kernel 3: per-(q,sp) OTAM both directions + class accumulate --------
__global__ void __launch_bounds__(128) k_otam(const int* __restrict__ labels,
                                              float* __restrict__ out) {
    int t = blockIdx.x * blockDim.x + threadIdx.x;
    if (t >= QN * SPN) return;
    int q = t / SPN;
    int sp = t - q * SPN;

    float na[8], nb[8];
    #pragma unroll
    for (int i = 0; i < 8; i++) na[i] = g_tfn[q * 8 + i];
    #pragma unroll
    for (int j = 0; j < 8; j++) nb[j] = g_sfn[sp * 8 + j];

    float d[8][8];
    #pragma unroll
    for (int i = 0; i < 8; i++) {
        const float4* p = reinterpret_cast<const float4*>(
            g_dot + (size_t)(q * 8 + i) * NPAD + sp * 8);
        float4 v0 = p[0];
        float4 v1 = p[1];
        float dv[8] = {v0.x, v0.y, v0.z, v0.w, v1.x, v1.y, v1.z, v1.w};
        #pragma unroll
        for (int j = 0; j < 8; j++) {
            float den = fmaf(na[i], nb[j], 0.01f);
            d[i][j] = 1.0f - dv[j] * __frcp_rn(den);
        }
    }

    float r = otam_dp<false>(d) + otam_dp<true>(d);
    int c = labels[sp];
    atomicAdd(&out[q * NCLS + c], -r * g_invcnt[c]);
}

// -------- launcher --------
extern "C" void kernel_launch(void* const* d_in, const int* in_sizes, int n_in,
                              void* d_out, int out_size) {
    const float* tf = (const float*)d_in[0];      // [2048, 8, 2048]
    const float* sf = (const float*)d_in[1];      // [100, 8, 2048]
    const int* labels = (const int*)d_in[2];      // [100]
    float* out = (float*)d_out;                   // [1, 2048, 20]

    k_zero<<<(out_size + 255) / 256, 256>>>(out, out_size);
    k_invcnt<<<1, 64>>>(labels);
    k_conv_norm<0><<<MROWS, 256>>>(tf);
    k_conv_norm<1><<<NPAD, 256>>>(sf);
    dim3 ggrid(NPAD / 64, MROWS / 64);
    k_gemm<<<ggrid, 256>>>();
    k_otam<<<(QN * SPN + 127) / 128, 128>>>(labels, out);
}

// round 3
// speedup vs baseline: 1.2565x; 1.2565x over previous
#include <cuda_runtime.h>
#include <cuda_bf16.h>
#include <mma.h>
#include <cstdint>

using namespace nvcuda;

// Problem dims
#define QN 2048
#define SN 8
#define DN 2048
#define SPN 100
#define NCLS 20
#define MROWS (QN * SN)          // 16384
#define NCOLS (SPN * SN)         // 800
#define NPAD 832                 // 13 * 64
#define LBDA 0.1f
#define ILBDA 10.0f

// GEMM tiling
#define BM 128
#define BN 64
#define BK 32
#define NST 3
#define PAD_K 48                 // row pitch in bf16 elems (96 B, 16B-multiple)
#define A_ST_ELEM (BM * PAD_K)   // 6144 elems
#define B_ST_ELEM (BN * PAD_K)   // 3072 elems
#define SM_BYTES ((NST * (A_ST_ELEM + B_ST_ELEM)) * 2)  // 55296

// -------- scratch (device globals; allocation-free kernel_launch) --------
__device__ __nv_bfloat16 g_A[(size_t)MROWS * DN];   // 64 MB
__device__ __nv_bfloat16 g_B[(size_t)NPAD * DN];    // 3.4 MB
__device__ float g_dot[(size_t)MROWS * NPAD];       // 54.5 MB
__device__ float g_tfn[MROWS];
__device__ float g_sfn[NPAD];
__device__ float g_invcnt[NCLS];

// -------- cp.async helpers (compute_103-safe) --------
__device__ __forceinline__ void cpa16(uint32_t saddr, const void* g) {
    asm volatile("cp.async.cg.shared.global [%0], [%1], 16;"
                 :: "r"(saddr), "l"(__cvta_generic_to_global(g)) : "memory");
}
__device__ __forceinline__ void cpa_commit() {
    asm volatile("cp.async.commit_group;" ::: "memory");
}
__device__ __forceinline__ void cpa_wait1() {
    asm volatile("cp.async.wait_group 1;" ::: "memory");
}
__device__ __forceinline__ uint32_t smem_u32(const void* p) {
    uint32_t a;
    asm("{ .reg .u64 t; cvta.to.shared.u64 t, %1; cvt.u32.u64 %0, t; }"
        : "=r"(a) : "l"(p));
    return a;
}

// -------- kernel 0: inverse class counts --------
__global__ void k_invcnt(const int* __restrict__ labels) {
    __shared__ int cnt[NCLS];
    if (threadIdx.x < NCLS) cnt[threadIdx.x] = 0;
    __syncthreads();
    for (int i = threadIdx.x; i < SPN; i += blockDim.x)
        atomicAdd(&cnt[labels[i]], 1);
    __syncthreads();
    if (threadIdx.x < NCLS) {
        int c = cnt[threadIdx.x];
        g_invcnt[threadIdx.x] = 1.0f / (float)(c > 0 ? c : 1);
    }
}

__global__ void k_zero(float* __restrict__ out, int n) {
    int i = blockIdx.x * blockDim.x + threadIdx.x;
    if (i < n) out[i] = 0.0f;
}

// -------- kernel 1: fp32 -> bf16 conversion + row L2 norms --------
template <int MODE>
__global__ void __launch_bounds__(256) k_conv_norm(const float* __restrict__ src) {
    const int C = DN;
    int r = blockIdx.x;
    __nv_bfloat16* dst = (MODE == 0) ? g_A : g_B;
    float* norms = (MODE == 0) ? g_tfn : g_sfn;
    const int valid = (MODE == 0) ? MROWS : NCOLS;

    __nv_bfloat162* drow = reinterpret_cast<__nv_bfloat162*>(dst + (size_t)r * C);
    float ssum = 0.0f;
    if (r < valid) {
        const float4* s = reinterpret_cast<const float4*>(src + (size_t)r * C);
        for (int i = threadIdx.x; i < C / 4; i += blockDim.x) {
            float4 v = s[i];
            ssum = fmaf(v.x, v.x, fmaf(v.y, v.y, fmaf(v.z, v.z, fmaf(v.w, v.w, ssum))));
            drow[2 * i]     = __floats2bfloat162_rn(v.x, v.y);
            drow[2 * i + 1] = __floats2bfloat162_rn(v.z, v.w);
        }
    } else {
        __nv_bfloat162 z = __floats2bfloat162_rn(0.f, 0.f);
        for (int i = threadIdx.x; i < C / 4; i += blockDim.x) {
            drow[2 * i] = z;
            drow[2 * i + 1] = z;
        }
    }
    #pragma unroll
    for (int o = 16; o; o >>= 1) ssum += __shfl_xor_sync(0xFFFFFFFFu, ssum, o);
    __shared__ float wsum[8];
    int lane = threadIdx.x & 31, wid = threadIdx.x >> 5;
    if (lane == 0) wsum[wid] = ssum;
    __syncthreads();
    if (threadIdx.x == 0) {
        float s = 0.f;
        #pragma unroll
        for (int i = 0; i < 8; i++) s += wsum[i];
        norms[r] = sqrtf(s);
    }
}

// -------- kernel 2: pipelined wmma GEMM: g_dot[M, NPAD] = A @ B^T --------
// 3-stage cp.async, CTA tile 128x64xK32, 8 warps (4M x 2N), warp tile 32x32.
__global__ void __launch_bounds__(256, 2) k_gemm() {
    extern __shared__ __align__(128) char smem_raw[];
    __nv_bfloat16* sA = reinterpret_cast<__nv_bfloat16*>(smem_raw);
    __nv_bfloat16* sB = sA + NST * A_ST_ELEM;
    uint32_t sA_u = smem_u32(sA);
    uint32_t sB_u = smem_u32(sB);

    const int tid = threadIdx.x;
    const int warp = tid >> 5;
    const int wm = warp >> 1;     // 0..3
    const int wn = warp & 1;      // 0..1
    const int bm = blockIdx.y * BM;
    const int bn = blockIdx.x * BN;

    // loader indices: A 512 chunks (2/thread), B 256 chunks (1/thread)
    const int ar0 = tid >> 2;            // rows for A chunk pair: ar0, ar0+64
    const int ac = (tid & 3) * 8;        // bf16 col offset 0,8,16,24
    const int br = tid >> 2;             // B row 0..63
    const __nv_bfloat16* gA0 = g_A + (size_t)(bm + ar0) * DN + ac;
    const __nv_bfloat16* gA1 = g_A + (size_t)(bm + ar0 + 64) * DN + ac;
    const __nv_bfloat16* gB0 = g_B + (size_t)(bn + br) * DN + ac;
    const uint32_t sa_off0 = (uint32_t)(ar0 * PAD_K + ac) * 2;
    const uint32_t sa_off1 = (uint32_t)((ar0 + 64) * PAD_K + ac) * 2;
    const uint32_t sb_off0 = (uint32_t)(br * PAD_K + ac) * 2;

    auto load_stage = [&](int s, int k0) {
        uint32_t abase = sA_u + (uint32_t)(s * A_ST_ELEM * 2);
        uint32_t bbase = sB_u + (uint32_t)(s * B_ST_ELEM * 2);
        cpa16(abase + sa_off0, gA0 + k0);
        cpa16(abase + sa_off1, gA1 + k0);
        cpa16(bbase + sb_off0, gB0 + k0);
    };

    wmma::fragment<wmma::accumulator, 16, 16, 16, float> acc[2][2];
    #pragma unroll
    for (int i = 0; i < 2; i++)
        #pragma unroll
        for (int j = 0; j < 2; j++)
            wmma::fill_fragment(acc[i][j], 0.0f);

    const int NSTG = DN / BK;  // 64

    // prologue: prefetch stages 0,1
    load_stage(0, 0);
    cpa_commit();
    load_stage(1, BK);
    cpa_commit();

    #pragma unroll 1
    for (int s = 0; s < NSTG; s++) {
        cpa_wait1();          // stage s resident
        __syncthreads();

        // issue next prefetch (empty commit keeps group arithmetic uniform)
        if (s + 2 < NSTG) load_stage((s + 2) % NST, (s + 2) * BK);
        cpa_commit();

        const __nv_bfloat16* As = sA + (s % NST) * A_ST_ELEM + wm * 32 * PAD_K;
        const __nv_bfloat16* Bs = sB + (s % NST) * B_ST_ELEM + wn * 32 * PAD_K;

        #pragma unroll
        for (int k16 = 0; k16 < BK; k16 += 16) {
            wmma::fragment<wmma::matrix_a, 16, 16, 16, __nv_bfloat16, wmma::row_major> af0, af1;
            wmma::fragment<wmma::matrix_b, 16, 16, 16, __nv_bfloat16, wmma::col_major> bf0, bf1;
            wmma::load_matrix_sync(af0, As + k16, PAD_K);
            wmma::load_matrix_sync(af1, As + 16 * PAD_K + k16, PAD_K);
            wmma::load_matrix_sync(bf0, Bs + k16, PAD_K);
            wmma::load_matrix_sync(bf1, Bs + 16 * PAD_K + k16, PAD_K);
            wmma::mma_sync(acc[0][0], af0, bf0, acc[0][0]);
            wmma::mma_sync(acc[0][1], af0, bf1, acc[0][1]);
            wmma::mma_sync(acc[1][0], af1, bf0, acc[1][0]);
            wmma::mma_sync(acc[1][1], af1, bf1, acc[1][1]);
        }
    }

    float* Cp = g_dot + (size_t)(bm + wm * 32) * NPAD + bn + wn * 32;
    #pragma unroll
    for (int i = 0; i < 2; i++)
        #pragma unroll
        for (int j = 0; j < 2; j++)
            wmma::store_matrix_sync(Cp + (size_t)(i * 16) * NPAD + j * 16,
                                    acc[i][j], NPAD, wmma::mem_row_major);
}

// -------- OTAM soft-DTW --------
__device__ __forceinline__ float softmin2(float a, float b) {
    float mn = fminf(a, b);
    float df = fabsf(a - b);
    return mn - LBDA * __logf(1.0f + __expf(-df * ILBDA));
}
__device__ __forceinline__ float softmin3(float a, float b, float c) {
    float mn = fminf(a, fminf(b, c));
    float s = __expf((mn - a) * ILBDA) + __expf((mn - b) * ILBDA) + __expf((mn - c) * ILBDA);
    return mn - LBDA * __logf(s);
}

template <bool TR>
__device__ __forceinline__ float otam_dp(const float d[8][8]) {
    float prev[10];
    prev[0] = 0.0f;
    #pragma unroll
    for (int m = 1; m <= 8; m++) {
        float v = TR ? d[m - 1][0] : d[0][m - 1];
        prev[m] = prev[m - 1] + v;
    }
    prev[9] = prev[8];
    #pragma unroll
    for (int i = 1; i < 8; i++) {
        float cur[10];
        cur[0] = 0.0f;
        {
            float v = TR ? d[0][i] : d[i][0];
            cur[1] = v + softmin3(prev[0], prev[1], 0.0f);
        }
        #pragma unroll
        for (int m = 2; m <= 8; m++) {
            float v = TR ? d[m - 1][i] : d[i][m - 1];
            cur[m] = v + softmin2(prev[m - 1], cur[m - 1]);
        }
        cur[9] = softmin3(prev[8], prev[9], cur[8]);
        #pragma unroll
        for (int m = 0; m < 10; m++) prev[m] = cur[m];
    }
    return prev[9];
}

// -------- kernel 3: per-(q,sp) OTAM both directions + class accumulate --------
__global__ void __launch_bounds__(128) k_otam(const int* __restrict__ labels,
                                              float* __restrict__ out) {
    int t = blockIdx.x * blockDim.x + threadIdx.x;
    if (t >= QN * SPN) return;
    int q = t / SPN;
    int sp = t - q * SPN;

    float na[8], nb[8];
    #pragma unroll
    for (int i = 0; i < 8; i++) na[i] = g_tfn[q * 8 + i];
    #pragma unroll
    for (int j = 0; j < 8; j++) nb[j] = g_sfn[sp * 8 + j];

    float d[8][8];
    #pragma unroll
    for (int i = 0; i < 8; i++) {
        const float4* p = reinterpret_cast<const float4*>(
            g_dot + (size_t)(q * 8 + i) * NPAD + sp * 8);
        float4 v0 = p[0];
        float4 v1 = p[1];
        float dv[8] = {v0.x, v0.y, v0.z, v0.w, v1.x, v1.y, v1.z, v1.w};
        #pragma unroll
        for (int j = 0; j < 8; j++) {
            float den = fmaf(na[i], nb[j], 0.01f);
            d[i][j] = 1.0f - dv[j] * __frcp_rn(den);
        }
    }

    float r = otam_dp<false>(d) + otam_dp<true>(d);
    int c = labels[sp];
    atomicAdd(&out[q * NCLS + c], -r * g_invcnt[c]);
}

// -------- launcher --------
extern "C" void kernel_launch(void* const* d_in, const int* in_sizes, int n_in,
                              void* d_out, int out_size) {
    const float* tf = (const float*)d_in[0];      // [2048, 8, 2048]
    const float* sf = (const float*)d_in[1];      // [100, 8, 2048]
    const int* labels = (const int*)d_in[2];      // [100]
    float* out = (float*)d_out;                   // [1, 2048, 20]

    cudaFuncSetAttribute(k_gemm, cudaFuncAttributeMaxDynamicSharedMemorySize, SM_BYTES);

    k_zero<<<(out_size + 255) / 256, 256>>>(out, out_size);
    k_invcnt<<<1, 64>>>(labels);
    k_conv_norm<0><<<MROWS, 256>>>(tf);
    k_conv_norm<1><<<NPAD, 256>>>(sf);
    dim3 ggrid(NPAD / BN, MROWS / BM);
    k_gemm<<<ggrid, 256, SM_BYTES>>>();
    k_otam<<<(QN * SPN + 127) / 128, 128>>>(labels, out);
}

// round 4
// speedup vs baseline: 1.6418x; 1.3067x over previous
#include <cuda_runtime.h>
#include <cuda_bf16.h>
#include <cstdint>

// Problem dims
#define QN 2048
#define SN 8
#define DN 2048
#define SPN 100
#define NCLS 20
#define MROWS (QN * SN)          // 16384
#define NCOLS (SPN * SN)         // 800
#define NPAD 896                 // 7 * 128
#define LBDA 0.1f
#define ILBDA 10.0f

// GEMM tiling
#define BM 256
#define BN 128
#define BK 32
#define NST 4
#define PITCH 40                 // bf16 elems per smem row (80 B, conflict-free for ldsm)
#define PITCHB 80
#define A_STG_B (BM * PITCHB)    // 20480
#define B_STG_B (BN * PITCHB)    // 10240
#define STG_B (A_STG_B + B_STG_B)
#define SM_BYTES (NST * STG_B)   // 122880

// -------- scratch (device globals; allocation-free kernel_launch) --------
__device__ __nv_bfloat16 g_A[(size_t)MROWS * DN];   // 64 MB
__device__ __nv_bfloat16 g_B[(size_t)NPAD * DN];    // 3.7 MB
__device__ float g_dot[(size_t)MROWS * NPAD];       // 58.7 MB
__device__ float g_tfn[MROWS];
__device__ float g_sfn[NPAD];
__device__ float g_invcnt[NCLS];

// -------- PTX helpers (compute_103-safe) --------
__device__ __forceinline__ void cpa16(uint32_t saddr, const void* g) {
    asm volatile("cp.async.cg.shared.global [%0], [%1], 16;"
                 :: "r"(saddr), "l"(__cvta_generic_to_global(g)) : "memory");
}
__device__ __forceinline__ void cpa_commit() {
    asm volatile("cp.async.commit_group;" ::: "memory");
}
__device__ __forceinline__ void cpa_wait2() {
    asm volatile("cp.async.wait_group 2;" ::: "memory");
}
__device__ __forceinline__ uint32_t smem_u32(const void* p) {
    uint32_t a;
    asm("{ .reg .u64 t; cvta.to.shared.u64 t, %1; cvt.u32.u64 %0, t; }"
        : "=r"(a) : "l"(p));
    return a;
}
#define LDSM4(r0, r1, r2, r3, addr)                                         \
    asm volatile("ldmatrix.sync.aligned.m8n8.x4.shared.b16 {%0,%1,%2,%3}, [%4];" \
                 : "=r"(r0), "=r"(r1), "=r"(r2), "=r"(r3) : "r"(addr))

__device__ __forceinline__ void mma16816(float* d, const uint32_t* a,
                                         uint32_t b0, uint32_t b1) {
    asm volatile(
        "mma.sync.aligned.m16n8k16.row.col.f32.bf16.bf16.f32 "
        "{%0,%1,%2,%3}, {%4,%5,%6,%7}, {%8,%9}, {%0,%1,%2,%3};"
        : "+f"(d[0]), "+f"(d[1]), "+f"(d[2]), "+f"(d[3])
        : "r"(a[0]), "r"(a[1]), "r"(a[2]), "r"(a[3]), "r"(b0), "r"(b1));
}

// -------- kernel 0: inverse class counts --------
__global__ void k_invcnt(const int* __restrict__ labels) {
    __shared__ int cnt[NCLS];
    if (threadIdx.x < NCLS) cnt[threadIdx.x] = 0;
    __syncthreads();
    for (int i = threadIdx.x; i < SPN; i += blockDim.x)
        atomicAdd(&cnt[labels[i]], 1);
    __syncthreads();
    if (threadIdx.x < NCLS) {
        int c = cnt[threadIdx.x];
        g_invcnt[threadIdx.x] = 1.0f / (float)(c > 0 ? c : 1);
    }
}

__global__ void k_zero(float* __restrict__ out, int n) {
    int i = blockIdx.x * blockDim.x + threadIdx.x;
    if (i < n) out[i] = 0.0f;
}

// -------- kernel 1: fp32 -> bf16 conversion + row L2 norms --------
template <int MODE>
__global__ void __launch_bounds__(256) k_conv_norm(const float* __restrict__ src) {
    const int C = DN;
    int r = blockIdx.x;
    __nv_bfloat16* dst = (MODE == 0) ? g_A : g_B;
    float* norms = (MODE == 0) ? g_tfn : g_sfn;
    const int valid = (MODE == 0) ? MROWS : NCOLS;

    __nv_bfloat162* drow = reinterpret_cast<__nv_bfloat162*>(dst + (size_t)r * C);
    float ssum = 0.0f;
    if (r < valid) {
        const float4* s = reinterpret_cast<const float4*>(src + (size_t)r * C);
        for (int i = threadIdx.x; i < C / 4; i += blockDim.x) {
            float4 v = s[i];
            ssum = fmaf(v.x, v.x, fmaf(v.y, v.y, fmaf(v.z, v.z, fmaf(v.w, v.w, ssum))));
            drow[2 * i]     = __floats2bfloat162_rn(v.x, v.y);
            drow[2 * i + 1] = __floats2bfloat162_rn(v.z, v.w);
        }
    } else {
        __nv_bfloat162 z = __floats2bfloat162_rn(0.f, 0.f);
        for (int i = threadIdx.x; i < C / 4; i += blockDim.x) {
            drow[2 * i] = z;
            drow[2 * i + 1] = z;
        }
    }
    #pragma unroll
    for (int o = 16; o; o >>= 1) ssum += __shfl_xor_sync(0xFFFFFFFFu, ssum, o);
    __shared__ float wsum[8];
    int lane = threadIdx.x & 31, wid = threadIdx.x >> 5;
    if (lane == 0) wsum[wid] = ssum;
    __syncthreads();
    if (threadIdx.x == 0) {
        float s = 0.f;
        #pragma unroll
        for (int i = 0; i < 8; i++) s += wsum[i];
        norms[r] = sqrtf(s);
    }
}

// -------- kernel 2: mma.sync GEMM: g_dot[M, NPAD] = A @ B^T --------
// CTA 256x128xK32, 8 warps (4M x 2N), warp tile 64x64, 4-stage cp.async.
__global__ void __launch_bounds__(256, 1) k_gemm() {
    extern __shared__ __align__(128) char smem_raw[];
    uint32_t sb = smem_u32(smem_raw);

    const int tid = threadIdx.x;
    const int lane = tid & 31;
    const int warp = tid >> 5;
    const int wm = warp >> 1;     // 0..3
    const int wn = warp & 1;      // 0..1
    const int bm = blockIdx.y * BM;
    const int bn = blockIdx.x * BN;

    // ---- loader setup: 16B chunks, 4 for A, 2 for B per thread ----
    const int lrow = tid >> 2;          // 0..63
    const int lcol = tid & 3;           // 16B column 0..3
    const __nv_bfloat16* gA = g_A + (size_t)(bm + lrow) * DN + lcol * 8;
    const __nv_bfloat16* gB = g_B + (size_t)(bn + lrow) * DN + lcol * 8;
    const uint32_t s_off = (uint32_t)(lrow * PITCHB + lcol * 16);

    float acc[4][8][4];
    #pragma unroll
    for (int i = 0; i < 4; i++)
        #pragma unroll
        for (int j = 0; j < 8; j++)
            #pragma unroll
            for (int k = 0; k < 4; k++) acc[i][j][k] = 0.0f;

    const int NSTG = DN / BK;  // 64

    auto load_stage = [&](int st, int k0) {
        uint32_t base = sb + (uint32_t)(st * STG_B);
        #pragma unroll
        for (int i = 0; i < 4; i++)
            cpa16(base + s_off + (uint32_t)(i * 64 * PITCHB),
                  gA + k0 + (size_t)i * 64 * DN);
        #pragma unroll
        for (int i = 0; i < 2; i++)
            cpa16(base + A_STG_B + s_off + (uint32_t)(i * 64 * PITCHB),
                  gB + k0 + (size_t)i * 64 * DN);
        cpa_commit();
    };

    // prologue: prefetch stages 0..2
    load_stage(0, 0);
    load_stage(1, BK);
    load_stage(2, 2 * BK);

    // per-warp ldsm bases (row term: lane&15)
    const uint32_t a_row = (uint32_t)((wm * 64 + (lane & 15)) * PITCHB);
    const uint32_t b_row = (uint32_t)(A_STG_B + (wn * 64 + (lane & 15)) * PITCHB);
    const uint32_t c_half = (uint32_t)((lane >> 4) * 16);

    #pragma unroll 1
    for (int s = 0; s < NSTG; s++) {
        cpa_wait2();
        __syncthreads();
        if (s + 3 < NSTG) load_stage((s + 3) & 3, (s + 3) * BK);
        else cpa_commit();

        uint32_t stb = sb + (uint32_t)((s & 3) * STG_B);
        uint32_t aB = stb + a_row + c_half;
        uint32_t bB = stb + b_row + c_half;

        #pragma unroll
        for (int k16 = 0; k16 < 2; k16++) {
            uint32_t co = (uint32_t)(k16 * 32);
            uint32_t a[4][4];
            #pragma unroll
            for (int i = 0; i < 4; i++)
                LDSM4(a[i][0], a[i][1], a[i][2], a[i][3],
                      aB + co + (uint32_t)(i * 16 * PITCHB));
            uint32_t b[4][4];
            #pragma unroll
            for (int j = 0; j < 4; j++)
                LDSM4(b[j][0], b[j][1], b[j][2], b[j][3],
                      bB + co + (uint32_t)(j * 16 * PITCHB));
            #pragma unroll
            for (int i = 0; i < 4; i++)
                #pragma unroll
                for (int j = 0; j < 4; j++) {
                    mma16816(acc[i][2 * j],     a[i], b[j][0], b[j][2]);
                    mma16816(acc[i][2 * j + 1], a[i], b[j][1], b[j][3]);
                }
        }
    }

    // epilogue: direct stores (thread layout of m16n8 D frags)
    const int r0 = bm + wm * 64 + (lane >> 2);
    const int c0 = bn + wn * 64 + (lane & 3) * 2;
    #pragma unroll
    for (int i = 0; i < 4; i++) {
        #pragma unroll
        for (int j = 0; j < 8; j++) {
            float* p0 = g_dot + (size_t)(r0 + i * 16) * NPAD + c0 + j * 8;
            float* p1 = p0 + (size_t)8 * NPAD;
            *reinterpret_cast<float2*>(p0) = make_float2(acc[i][j][0], acc[i][j][1]);
            *reinterpret_cast<float2*>(p1) = make_float2(acc[i][j][2], acc[i][j][3]);
        }
    }
}

// -------- OTAM soft-DTW --------
__device__ __forceinline__ float softmin2(float a, float b) {
    float mn = fminf(a, b);
    float df = fabsf(a - b);
    return mn - LBDA * __logf(1.0f + __expf(-df * ILBDA));
}
__device__ __forceinline__ float softmin3(float a, float b, float c) {
    float mn = fminf(a, fminf(b, c));
    float s = __expf((mn - a) * ILBDA) + __expf((mn - b) * ILBDA) + __expf((mn - c) * ILBDA);
    return mn - LBDA * __logf(s);
}

template <bool TR>
__device__ __forceinline__ float otam_dp(const float d[8][8]) {
    float prev[10];
    prev[0] = 0.0f;
    #pragma unroll
    for (int m = 1; m <= 8; m++) {
        float v = TR ? d[m - 1][0] : d[0][m - 1];
        prev[m] = prev[m - 1] + v;
    }
    prev[9] = prev[8];
    #pragma unroll
    for (int i = 1; i < 8; i++) {
        float cur[10];
        cur[0] = 0.0f;
        {
            float v = TR ? d[0][i] : d[i][0];
            cur[1] = v + softmin3(prev[0], prev[1], 0.0f);
        }
        #pragma unroll
        for (int m = 2; m <= 8; m++) {
            float v = TR ? d[m - 1][i] : d[i][m - 1];
            cur[m] = v + softmin2(prev[m - 1], cur[m - 1]);
        }
        cur[9] = softmin3(prev[8], prev[9], cur[8]);
        #pragma unroll
        for (int m = 0; m < 10; m++) prev[m] = cur[m];
    }
    return prev[9];
}

// -------- kernel 3: per-(q,sp) OTAM both directions + class accumulate --------
__global__ void __launch_bounds__(128) k_otam(const int* __restrict__ labels,
                                              float* __restrict__ out) {
    int t = blockIdx.x * blockDim.x + threadIdx.x;
    if (t >= QN * SPN) return;
    int q = t / SPN;
    int sp = t - q * SPN;

    float na[8], nb[8];
    #pragma unroll
    for (int i = 0; i < 8; i++) na[i] = g_tfn[q * 8 + i];
    #pragma unroll
    for (int j = 0; j < 8; j++) nb[j] = g_sfn[sp * 8 + j];

    float d[8][8];
    #pragma unroll
    for (int i = 0; i < 8; i++) {
        const float4* p = reinterpret_cast<const float4*>(
            g_dot + (size_t)(q * 8 + i) * NPAD + sp * 8);
        float4 v0 = p[0];
        float4 v1 = p[1];
        float dv[8] = {v0.x, v0.y, v0.z, v0.w, v1.x, v1.y, v1.z, v1.w};
        #pragma unroll
        for (int j = 0; j < 8; j++) {
            float den = fmaf(na[i], nb[j], 0.01f);
            d[i][j] = 1.0f - dv[j] * __frcp_rn(den);
        }
    }

    float r = otam_dp<false>(d) + otam_dp<true>(d);
    int c = labels[sp];
    atomicAdd(&out[q * NCLS + c], -r * g_invcnt[c]);
}

// -------- launcher --------
extern "C" void kernel_launch(void* const* d_in, const int* in_sizes, int n_in,
                              void* d_out, int out_size) {
    const float* tf = (const float*)d_in[0];      // [2048, 8, 2048]
    const float* sf = (const float*)d_in[1];      // [100, 8, 2048]
    const int* labels = (const int*)d_in[2];      // [100]
    float* out = (float*)d_out;                   // [1, 2048, 20]

    cudaFuncSetAttribute(k_gemm, cudaFuncAttributeMaxDynamicSharedMemorySize, SM_BYTES);

    k_zero<<<(out_size + 255) / 256, 256>>>(out, out_size);
    k_invcnt<<<1, 64>>>(labels);
    k_conv_norm<0><<<MROWS, 256>>>(tf);
    k_conv_norm<1><<<NPAD, 256>>>(sf);
    dim3 ggrid(NPAD / BN, MROWS / BM);
    k_gemm<<<ggrid, 256, SM_BYTES>>>();
    k_otam<<<(QN * SPN + 127) / 128, 128>>>(labels, out);
}

// round 5
// speedup vs baseline: 2.0257x; 1.2338x over previous
#include <cuda_runtime.h>
#include <cuda_bf16.h>
#include <cstdint>

// Problem dims
#define QN 2048
#define SN 8
#define DN 2048
#define SPN 100
#define NCLS 20
#define MROWS (QN * SN)          // 16384
#define NCOLS (SPN * SN)         // 800
#define NPAD 896                 // 7 * 128
#define LBDA 0.1f
#define ILBDA 10.0f

// GEMM tiling: CTA 256x128 x K64, SW128-swizzled smem, 3-stage cp.async
#define BM 256
#define BN 128
#define BK 64
#define NST 3
#define A_STG_B (BM * 128)       // 32768
#define B_STG_B (BN * 128)       // 16384
#define STG_B (A_STG_B + B_STG_B)
#define SM_BYTES (NST * STG_B)   // 147456

// -------- scratch (device globals; allocation-free kernel_launch) --------
__device__ __nv_bfloat16 g_A[(size_t)MROWS * DN];   // 64 MB
__device__ __nv_bfloat16 g_B[(size_t)NPAD * DN];    // 3.7 MB
__device__ float g_dot[(size_t)MROWS * NPAD];       // 58.7 MB
__device__ float g_tfn[MROWS];
__device__ float g_sfn[NPAD];
__device__ float g_invcnt[NCLS];

// -------- PTX helpers (compute_103-safe) --------
__device__ __forceinline__ void cpa16(uint32_t saddr, const void* g) {
    asm volatile("cp.async.cg.shared.global [%0], [%1], 16;"
                 :: "r"(saddr), "l"(__cvta_generic_to_global(g)) : "memory");
}
__device__ __forceinline__ void cpa_commit() {
    asm volatile("cp.async.commit_group;" ::: "memory");
}
__device__ __forceinline__ void cpa_wait1() {
    asm volatile("cp.async.wait_group 1;" ::: "memory");
}
__device__ __forceinline__ uint32_t smem_u32(const void* p) {
    uint32_t a;
    asm("{ .reg .u64 t; cvta.to.shared.u64 t, %1; cvt.u32.u64 %0, t; }"
        : "=r"(a) : "l"(p));
    return a;
}
#define LDSM4(r0, r1, r2, r3, addr)                                         \
    asm volatile("ldmatrix.sync.aligned.m8n8.x4.shared.b16 {%0,%1,%2,%3}, [%4];" \
                 : "=r"(r0), "=r"(r1), "=r"(r2), "=r"(r3) : "r"(addr))

__device__ __forceinline__ void mma16816(float* d, const uint32_t* a,
                                         uint32_t b0, uint32_t b1) {
    asm volatile(
        "mma.sync.aligned.m16n8k16.row.col.f32.bf16.bf16.f32 "
        "{%0,%1,%2,%3}, {%4,%5,%6,%7}, {%8,%9}, {%0,%1,%2,%3};"
        : "+f"(d[0]), "+f"(d[1]), "+f"(d[2]), "+f"(d[3])
        : "r"(a[0]), "r"(a[1]), "r"(a[2]), "r"(a[3]), "r"(b0), "r"(b1));
}

// -------- kernel 0: inverse class counts --------
__global__ void k_invcnt(const int* __restrict__ labels) {
    __shared__ int cnt[NCLS];
    if (threadIdx.x < NCLS) cnt[threadIdx.x] = 0;
    __syncthreads();
    for (int i = threadIdx.x; i < SPN; i += blockDim.x)
        atomicAdd(&cnt[labels[i]], 1);
    __syncthreads();
    if (threadIdx.x < NCLS) {
        int c = cnt[threadIdx.x];
        g_invcnt[threadIdx.x] = 1.0f / (float)(c > 0 ? c : 1);
    }
}

__global__ void k_zero(float* __restrict__ out, int n) {
    int i = blockIdx.x * blockDim.x + threadIdx.x;
    if (i < n) out[i] = 0.0f;
}

// -------- kernel 1: fp32 -> bf16 + row L2 norms (4 rows/block, MLP=8) ----
template <int MODE>
__global__ void __launch_bounds__(256) k_conv_norm(const float* __restrict__ src) {
    const int rg = threadIdx.x >> 6;      // row group 0..3
    const int t = threadIdx.x & 63;       // 64 threads per row
    const int row = blockIdx.x * 4 + rg;
    __nv_bfloat16* dst = (MODE == 0) ? g_A : g_B;
    float* norms = (MODE == 0) ? g_tfn : g_sfn;
    const int valid = (MODE == 0) ? MROWS : NCOLS;

    uint2* drow = reinterpret_cast<uint2*>(dst + (size_t)row * DN);
    float ss = 0.0f;
    if (row < valid) {
        const float4* s = reinterpret_cast<const float4*>(src + (size_t)row * DN);
        float4 v[8];
        #pragma unroll
        for (int j = 0; j < 8; j++) v[j] = s[t + 64 * j];
        #pragma unroll
        for (int j = 0; j < 8; j++) {
            ss = fmaf(v[j].x, v[j].x, fmaf(v[j].y, v[j].y,
                 fmaf(v[j].z, v[j].z, fmaf(v[j].w, v[j].w, ss))));
            __nv_bfloat162 lo = __floats2bfloat162_rn(v[j].x, v[j].y);
            __nv_bfloat162 hi = __floats2bfloat162_rn(v[j].z, v[j].w);
            drow[t + 64 * j] = make_uint2(*reinterpret_cast<uint32_t*>(&lo),
                                          *reinterpret_cast<uint32_t*>(&hi));
        }
    } else {
        #pragma unroll
        for (int j = 0; j < 8; j++)
            drow[t + 64 * j] = make_uint2(0u, 0u);
    }
    #pragma unroll
    for (int o = 16; o; o >>= 1) ss += __shfl_xor_sync(0xFFFFFFFFu, ss, o);
    __shared__ float ws[8];
    if ((threadIdx.x & 31) == 0) ws[threadIdx.x >> 5] = ss;
    __syncthreads();
    if (t == 0 && row < valid)
        norms[row] = sqrtf(ws[rg * 2] + ws[rg * 2 + 1]);
}

// -------- kernel 2: mma.sync GEMM, SW128 swizzle: g_dot = A @ B^T --------
__global__ void __launch_bounds__(256, 1) k_gemm() {
    extern __shared__ __align__(128) char smem_raw[];
    uint32_t sb = smem_u32(smem_raw);

    const int tid = threadIdx.x;
    const int lane = tid & 31;
    const int warp = tid >> 5;
    const int wm = warp >> 1;     // 0..3
    const int wn = warp & 1;      // 0..1
    const int bm = blockIdx.y * BM;
    const int bn = blockIdx.x * BN;

    // ---- loader: 16B chunks; thread -> (row tid>>3, chunk tid&7), rows +=32
    const int lrow = tid >> 3;          // 0..31
    const int lcc = tid & 7;            // chunk 0..7 (k-offset lcc*8 bf16)
    const uint32_t s_off =
        (uint32_t)(lrow * 128 + ((lcc ^ (lrow & 7)) << 4));
    const __nv_bfloat16* gA = g_A + (size_t)(bm + lrow) * DN + lcc * 8;
    const __nv_bfloat16* gB = g_B + (size_t)(bn + lrow) * DN + lcc * 8;

    float acc[4][8][4];
    #pragma unroll
    for (int i = 0; i < 4; i++)
        #pragma unroll
        for (int j = 0; j < 8; j++)
            #pragma unroll
            for (int k = 0; k < 4; k++) acc[i][j][k] = 0.0f;

    const int NSTG = DN / BK;  // 32

    auto load_stage = [&](int st, int k0) {
        uint32_t base = sb + (uint32_t)(st * STG_B);
        #pragma unroll
        for (int i = 0; i < 8; i++)
            cpa16(base + s_off + (uint32_t)(i * 32 * 128),
                  gA + k0 + (size_t)i * 32 * DN);
        #pragma unroll
        for (int i = 0; i < 4; i++)
            cpa16(base + A_STG_B + s_off + (uint32_t)(i * 32 * 128),
                  gB + k0 + (size_t)i * 32 * DN);
        cpa_commit();
    };

    load_stage(0, 0);
    load_stage(1, BK);

    // per-lane ldsm bases: row = warpbase + frag*16 + (lane&15); row&7 == lane&7
    const uint32_t hl = (uint32_t)(lane >> 4);      // 16B half select
    const uint32_t l7 = (uint32_t)(lane & 7);
    const uint32_t aRow = (uint32_t)((wm * 64 + (lane & 15)) * 128);
    const uint32_t bRow = (uint32_t)(A_STG_B + (wn * 64 + (lane & 15)) * 128);

    #pragma unroll 1
    for (int s = 0; s < NSTG; s++) {
        cpa_wait1();
        __syncthreads();
        if (s + 2 < NSTG) load_stage((s + 2) % NST, (s + 2) * BK);
        else cpa_commit();

        uint32_t stb = sb + (uint32_t)((s % NST) * STG_B);

        #pragma unroll
        for (int kk = 0; kk < 4; kk++) {
            uint32_t xc = (((uint32_t)(2 * kk) + hl) ^ l7) << 4;
            uint32_t a[4][4];
            #pragma unroll
            for (int i = 0; i < 4; i++)
                LDSM4(a[i][0], a[i][1], a[i][2], a[i][3],
                      stb + aRow + (uint32_t)(i * 16 * 128) + xc);
            uint32_t b[4][4];
            #pragma unroll
            for (int j = 0; j < 4; j++)
                LDSM4(b[j][0], b[j][1], b[j][2], b[j][3],
                      stb + bRow + (uint32_t)(j * 16 * 128) + xc);
            #pragma unroll
            for (int i = 0; i < 4; i++)
                #pragma unroll
                for (int j = 0; j < 4; j++) {
                    mma16816(acc[i][2 * j],     a[i], b[j][0], b[j][2]);
                    mma16816(acc[i][2 * j + 1], a[i], b[j][1], b[j][3]);
                }
        }
    }

    // epilogue: direct stores
    const int r0 = bm + wm * 64 + (lane >> 2);
    const int c0 = bn + wn * 64 + (lane & 3) * 2;
    #pragma unroll
    for (int i = 0; i < 4; i++) {
        #pragma unroll
        for (int j = 0; j < 8; j++) {
            float* p0 = g_dot + (size_t)(r0 + i * 16) * NPAD + c0 + j * 8;
            float* p1 = p0 + (size_t)8 * NPAD;
            *reinterpret_cast<float2*>(p0) = make_float2(acc[i][j][0], acc[i][j][1]);
            *reinterpret_cast<float2*>(p1) = make_float2(acc[i][j][2], acc[i][j][3]);
        }
    }
}

// -------- OTAM soft-DTW --------
__device__ __forceinline__ float softmin2(float a, float b) {
    float mn = fminf(a, b);
    float df = fabsf(a - b);
    return mn - LBDA * __logf(1.0f + __expf(-df * ILBDA));
}
__device__ __forceinline__ float softmin3(float a, float b, float c) {
    float mn = fminf(a, fminf(b, c));
    float s = __expf((mn - a) * ILBDA) + __expf((mn - b) * ILBDA) + __expf((mn - c) * ILBDA);
    return mn - LBDA * __logf(s);
}

template <bool TR>
__device__ __forceinline__ float otam_dp(const float d[8][8]) {
    float prev[10];
    prev[0] = 0.0f;
    #pragma unroll
    for (int m = 1; m <= 8; m++) {
        float v = TR ? d[m - 1][0] : d[0][m - 1];
        prev[m] = prev[m - 1] + v;
    }
    prev[9] = prev[8];
    #pragma unroll
    for (int i = 1; i < 8; i++) {
        float cur[10];
        cur[0] = 0.0f;
        {
            float v = TR ? d[0][i] : d[i][0];
            cur[1] = v + softmin3(prev[0], prev[1], 0.0f);
        }
        #pragma unroll
        for (int m = 2; m <= 8; m++) {
            float v = TR ? d[m - 1][i] : d[i][m - 1];
            cur[m] = v + softmin2(prev[m - 1], cur[m - 1]);
        }
        cur[9] = softmin3(prev[8], prev[9], cur[8]);
        #pragma unroll
        for (int m = 0; m < 10; m++) prev[m] = cur[m];
    }
    return prev[9];
}

// -------- kernel 3: per-(q,sp) OTAM both directions + class accumulate --------
__global__ void __launch_bounds__(128) k_otam(const int* __restrict__ labels,
                                              float* __restrict__ out) {
    int t = blockIdx.x * blockDim.x + threadIdx.x;
    if (t >= QN * SPN) return;
    int q = t / SPN;
    int sp = t - q * SPN;

    float na[8], nb[8];
    #pragma unroll
    for (int i = 0; i < 8; i++) na[i] = g_tfn[q * 8 + i];
    #pragma unroll
    for (int j = 0; j < 8; j++) nb[j] = g_sfn[sp * 8 + j];

    float d[8][8];
    #pragma unroll
    for (int i = 0; i < 8; i++) {
        const float4* p = reinterpret_cast<const float4*>(
            g_dot + (size_t)(q * 8 + i) * NPAD + sp * 8);
        float4 v0 = p[0];
        float4 v1 = p[1];
        float dv[8] = {v0.x, v0.y, v0.z, v0.w, v1.x, v1.y, v1.z, v1.w};
        #pragma unroll
        for (int j = 0; j < 8; j++) {
            float den = fmaf(na[i], nb[j], 0.01f);
            d[i][j] = 1.0f - dv[j] * __frcp_rn(den);
        }
    }

    float r = otam_dp<false>(d) + otam_dp<true>(d);
    int c = labels[sp];
    atomicAdd(&out[q * NCLS + c], -r * g_invcnt[c]);
}

// -------- launcher --------
extern "C" void kernel_launch(void* const* d_in, const int* in_sizes, int n_in,
                              void* d_out, int out_size) {
    const float* tf = (const float*)d_in[0];      // [2048, 8, 2048]
    const float* sf = (const float*)d_in[1];      // [100, 8, 2048]
    const int* labels = (const int*)d_in[2];      // [100]
    float* out = (float*)d_out;                   // [1, 2048, 20]

    cudaFuncSetAttribute(k_gemm, cudaFuncAttributeMaxDynamicSharedMemorySize, SM_BYTES);

    k_zero<<<(out_size + 255) / 256, 256>>>(out, out_size);
    k_invcnt<<<1, 64>>>(labels);
    k_conv_norm<0><<<MROWS / 4, 256>>>(tf);
    k_conv_norm<1><<<NPAD / 4, 256>>>(sf);
    dim3 ggrid(NPAD / BN, MROWS / BM);
    k_gemm<<<ggrid, 256, SM_BYTES>>>();
    k_otam<<<(QN * SPN + 127) / 128, 128>>>(labels, out);
}

// round 6
// speedup vs baseline: 2.1549x; 1.0638x over previous
#include <cuda_runtime.h>
#include <cuda_bf16.h>
#include <cstdint>

// Problem dims
#define QN 2048
#define SN 8
#define DN 2048
#define SPN 100
#define NCLS 20
#define MROWS (QN * SN)          // 16384
#define NCOLS (SPN * SN)         // 800
#define NPAD 896                 // 7 * 128
#define LBDA 0.1f
#define ILBDA 10.0f
#define FP8SCALE 16.0f
#define INV256 0.00390625f

// GEMM tiling: CTA 256x128 x K128(fp8), SW128-swizzled smem, 3-stage cp.async
#define BM 256
#define BN 128
#define BK 128                   // fp8 elems = 128 B rows
#define NST 3
#define A_STG_B (BM * 128)       // 32768
#define B_STG_B (BN * 128)       // 16384
#define STG_B (A_STG_B + B_STG_B)
#define SM_BYTES (NST * STG_B)   // 147456

// -------- scratch (device globals; allocation-free kernel_launch) --------
__device__ uint8_t g_A[(size_t)MROWS * DN];   // 32 MB (e4m3)
__device__ uint8_t g_B[(size_t)NPAD * DN];    // 1.8 MB (e4m3)
__device__ float g_dot[(size_t)MROWS * NPAD]; // 58.7 MB
__device__ float g_tfn[MROWS];
__device__ float g_sfn[NPAD];
__device__ float g_invcnt[NCLS];

// -------- PTX helpers (compute_103-safe) --------
__device__ __forceinline__ void cpa16(uint32_t saddr, const void* g) {
    asm volatile("cp.async.cg.shared.global [%0], [%1], 16;"
                 :: "r"(saddr), "l"(__cvta_generic_to_global(g)) : "memory");
}
__device__ __forceinline__ void cpa_commit() {
    asm volatile("cp.async.commit_group;" ::: "memory");
}
__device__ __forceinline__ void cpa_wait1() {
    asm volatile("cp.async.wait_group 1;" ::: "memory");
}
__device__ __forceinline__ uint32_t smem_u32(const void* p) {
    uint32_t a;
    asm("{ .reg .u64 t; cvta.to.shared.u64 t, %1; cvt.u32.u64 %0, t; }"
        : "=r"(a) : "l"(p));
    return a;
}
#define LDSM4(r0, r1, r2, r3, addr)                                         \
    asm volatile("ldmatrix.sync.aligned.m8n8.x4.shared.b16 {%0,%1,%2,%3}, [%4];" \
                 : "=r"(r0), "=r"(r1), "=r"(r2), "=r"(r3) : "r"(addr))

__device__ __forceinline__ void mma_fp8(float* d, const uint32_t* a,
                                        uint32_t b0, uint32_t b1) {
    asm volatile(
        "mma.sync.aligned.m16n8k32.row.col.f32.e4m3.e4m3.f32 "
        "{%0,%1,%2,%3}, {%4,%5,%6,%7}, {%8,%9}, {%0,%1,%2,%3};"
        : "+f"(d[0]), "+f"(d[1]), "+f"(d[2]), "+f"(d[3])
        : "r"(a[0]), "r"(a[1]), "r"(a[2]), "r"(a[3]), "r"(b0), "r"(b1));
}
// pack two floats -> two e4m3 bytes: low byte = e0, high byte = e1
__device__ __forceinline__ uint16_t f2e4m3x2(float e0, float e1) {
    uint16_t r;
    asm("cvt.rn.satfinite.e4m3x2.f32 %0, %1, %2;" : "=h"(r) : "f"(e1), "f"(e0));
    return r;
}

// -------- kernel 0: zero output + class inverse counts --------
__global__ void k_zero(float* __restrict__ out, int n,
                       const int* __restrict__ labels) {
    int i = blockIdx.x * blockDim.x + threadIdx.x;
    if (i < n) out[i] = 0.0f;
    if (blockIdx.x == 0) {
        __shared__ int cnt[NCLS];
        if (threadIdx.x < NCLS) cnt[threadIdx.x] = 0;
        __syncthreads();
        if (threadIdx.x < SPN) atomicAdd(&cnt[labels[threadIdx.x]], 1);
        __syncthreads();
        if (threadIdx.x < NCLS) {
            int c = cnt[threadIdx.x];
            g_invcnt[threadIdx.x] = 1.0f / (float)(c > 0 ? c : 1);
        }
    }
}

// -------- kernel 1: fp32 -> e4m3 (x16 scale) + fp32 row L2 norms --------
// One unified grid: rows [0, MROWS) -> A from tf; rows [MROWS, MROWS+NPAD) -> B.
// 2 rows per 256-thr block, 128 thr/row, 16 floats (4 float4) per thread.
__global__ void __launch_bounds__(256) k_conv(const float* __restrict__ tf,
                                              const float* __restrict__ sf) {
    const int rg = threadIdx.x >> 7;      // 0..1
    const int t = threadIdx.x & 127;
    int row = blockIdx.x * 2 + rg;

    const float* src;
    uint8_t* dst;
    float* norms;
    bool pad = false;
    if (row < MROWS) {
        src = tf + (size_t)row * DN;
        dst = g_A + (size_t)row * DN;
        norms = &g_tfn[row];
    } else {
        int r = row - MROWS;
        pad = (r >= NCOLS);
        src = sf + (size_t)r * DN;
        dst = g_B + (size_t)r * DN;
        norms = &g_sfn[r];
    }

    float ss = 0.0f;
    uint4 outv = make_uint4(0u, 0u, 0u, 0u);
    if (!pad) {
        const float4* s = reinterpret_cast<const float4*>(src);
        float4 v[4];
        #pragma unroll
        for (int j = 0; j < 4; j++) v[j] = s[t * 4 + j];
        uint16_t h[8];
        #pragma unroll
        for (int j = 0; j < 4; j++) {
            ss = fmaf(v[j].x, v[j].x, fmaf(v[j].y, v[j].y,
                 fmaf(v[j].z, v[j].z, fmaf(v[j].w, v[j].w, ss))));
            h[2 * j]     = f2e4m3x2(v[j].x * FP8SCALE, v[j].y * FP8SCALE);
            h[2 * j + 1] = f2e4m3x2(v[j].z * FP8SCALE, v[j].w * FP8SCALE);
        }
        outv.x = (uint32_t)h[0] | ((uint32_t)h[1] << 16);
        outv.y = (uint32_t)h[2] | ((uint32_t)h[3] << 16);
        outv.z = (uint32_t)h[4] | ((uint32_t)h[5] << 16);
        outv.w = (uint32_t)h[6] | ((uint32_t)h[7] << 16);
    }
    reinterpret_cast<uint4*>(dst)[t] = outv;

    #pragma unroll
    for (int o = 16; o; o >>= 1) ss += __shfl_xor_sync(0xFFFFFFFFu, ss, o);
    __shared__ float ws[8];
    if ((threadIdx.x & 31) == 0) ws[threadIdx.x >> 5] = ss;
    __syncthreads();
    if (t == 0)
        *norms = sqrtf(ws[rg * 4] + ws[rg * 4 + 1] + ws[rg * 4 + 2] + ws[rg * 4 + 3]);
}

// -------- kernel 2: fp8 mma.sync GEMM, SW128 swizzle: g_dot = A @ B^T -----
__global__ void __launch_bounds__(256, 1) k_gemm() {
    extern __shared__ __align__(128) char smem_raw[];
    uint32_t sb = smem_u32(smem_raw);

    const int tid = threadIdx.x;
    const int lane = tid & 31;
    const int warp = tid >> 5;
    const int wm = warp >> 1;     // 0..3
    const int wn = warp & 1;      // 0..1
    const int bm = blockIdx.y * BM;
    const int bn = blockIdx.x * BN;

    // loader: 16B chunks; thread -> (row tid>>3, chunk tid&7), rows += 32
    const int lrow = tid >> 3;          // 0..31
    const int lcc = tid & 7;            // 16B chunk in 128B row
    const uint32_t s_off =
        (uint32_t)(lrow * 128 + ((lcc ^ (lrow & 7)) << 4));
    const uint8_t* gA = g_A + (size_t)(bm + lrow) * DN + lcc * 16;
    const uint8_t* gB = g_B + (size_t)(bn + lrow) * DN + lcc * 16;

    float acc[4][8][4];
    #pragma unroll
    for (int i = 0; i < 4; i++)
        #pragma unroll
        for (int j = 0; j < 8; j++)
            #pragma unroll
            for (int k = 0; k < 4; k++) acc[i][j][k] = 0.0f;

    const int NSTG = DN / BK;  // 16

    auto load_stage = [&](int st, int k0) {
        uint32_t base = sb + (uint32_t)(st * STG_B);
        #pragma unroll
        for (int i = 0; i < 8; i++)
            cpa16(base + s_off + (uint32_t)(i * 32 * 128),
                  gA + k0 + (size_t)i * 32 * DN);
        #pragma unroll
        for (int i = 0; i < 4; i++)
            cpa16(base + A_STG_B + s_off + (uint32_t)(i * 32 * 128),
                  gB + k0 + (size_t)i * 32 * DN);
        cpa_commit();
    };

    load_stage(0, 0);
    load_stage(1, BK);

    const uint32_t hl = (uint32_t)(lane >> 4);      // 16B half of 32B chunk
    const uint32_t l7 = (uint32_t)(lane & 7);
    const uint32_t aRow = (uint32_t)((wm * 64 + (lane & 15)) * 128);
    const uint32_t bRow = (uint32_t)(A_STG_B + (wn * 64 + (lane & 15)) * 128);

    #pragma unroll 1
    for (int s = 0; s < NSTG; s++) {
        cpa_wait1();
        __syncthreads();
        if (s + 2 < NSTG) load_stage((s + 2) % NST, (s + 2) * BK);
        else cpa_commit();

        uint32_t stb = sb + (uint32_t)((s % NST) * STG_B);

        #pragma unroll
        for (int kk = 0; kk < 4; kk++) {        // 4 x k32 per 128B row
            uint32_t xc = (((uint32_t)(2 * kk) + hl) ^ l7) << 4;
            uint32_t a[4][4];
            #pragma unroll
            for (int i = 0; i < 4; i++)
                LDSM4(a[i][0], a[i][1], a[i][2], a[i][3],
                      stb + aRow + (uint32_t)(i * 16 * 128) + xc);
            uint32_t b[4][4];
            #pragma unroll
            for (int j = 0; j < 4; j++)
                LDSM4(b[j][0], b[j][1], b[j][2], b[j][3],
                      stb + bRow + (uint32_t)(j * 16 * 128) + xc);
            #pragma unroll
            for (int i = 0; i < 4; i++)
                #pragma unroll
                for (int j = 0; j < 4; j++) {
                    mma_fp8(acc[i][2 * j],     a[i], b[j][0], b[j][2]);
                    mma_fp8(acc[i][2 * j + 1], a[i], b[j][1], b[j][3]);
                }
        }
    }

    // epilogue: direct stores
    const int r0 = bm + wm * 64 + (lane >> 2);
    const int c0 = bn + wn * 64 + (lane & 3) * 2;
    #pragma unroll
    for (int i = 0; i < 4; i++) {
        #pragma unroll
        for (int j = 0; j < 8; j++) {
            float* p0 = g_dot + (size_t)(r0 + i * 16) * NPAD + c0 + j * 8;
            float* p1 = p0 + (size_t)8 * NPAD;
            *reinterpret_cast<float2*>(p0) = make_float2(acc[i][j][0], acc[i][j][1]);
            *reinterpret_cast<float2*>(p1) = make_float2(acc[i][j][2], acc[i][j][3]);
        }
    }
}

// -------- OTAM soft-DTW --------
__device__ __forceinline__ float softmin2(float a, float b) {
    float mn = fminf(a, b);
    float df = fabsf(a - b);
    return mn - LBDA * __logf(1.0f + __expf(-df * ILBDA));
}
__device__ __forceinline__ float softmin3(float a, float b, float c) {
    float mn = fminf(a, fminf(b, c));
    float s = __expf((mn - a) * ILBDA) + __expf((mn - b) * ILBDA) + __expf((mn - c) * ILBDA);
    return mn - LBDA * __logf(s);
}

template <bool TR>
__device__ __forceinline__ float otam_dp(const float d[8][8]) {
    float prev[10];
    prev[0] = 0.0f;
    #pragma unroll
    for (int m = 1; m <= 8; m++) {
        float v = TR ? d[m - 1][0] : d[0][m - 1];
        prev[m] = prev[m - 1] + v;
    }
    prev[9] = prev[8];
    #pragma unroll
    for (int i = 1; i < 8; i++) {
        float cur[10];
        cur[0] = 0.0f;
        {
            float v = TR ? d[0][i] : d[i][0];
            cur[1] = v + softmin3(prev[0], prev[1], 0.0f);
        }
        #pragma unroll
        for (int m = 2; m <= 8; m++) {
            float v = TR ? d[m - 1][i] : d[i][m - 1];
            cur[m] = v + softmin2(prev[m - 1], cur[m - 1]);
        }
        cur[9] = softmin3(prev[8], prev[9], cur[8]);
        #pragma unroll
        for (int m = 0; m < 10; m++) prev[m] = cur[m];
    }
    return prev[9];
}

// -------- kernel 3: per-(q,sp) OTAM both directions + class accumulate --------
__global__ void __launch_bounds__(128) k_otam(const int* __restrict__ labels,
                                              float* __restrict__ out) {
    int t = blockIdx.x * blockDim.x + threadIdx.x;
    if (t >= QN * SPN) return;
    int q = t / SPN;
    int sp = t - q * SPN;

    float na[8], nb[8];
    #pragma unroll
    for (int i = 0; i < 8; i++) na[i] = g_tfn[q * 8 + i];
    #pragma unroll
    for (int j = 0; j < 8; j++) nb[j] = g_sfn[sp * 8 + j];

    float d[8][8];
    #pragma unroll
    for (int i = 0; i < 8; i++) {
        const float4* p = reinterpret_cast<const float4*>(
            g_dot + (size_t)(q * 8 + i) * NPAD + sp * 8);
        float4 v0 = p[0];
        float4 v1 = p[1];
        float dv[8] = {v0.x, v0.y, v0.z, v0.w, v1.x, v1.y, v1.z, v1.w};
        #pragma unroll
        for (int j = 0; j < 8; j++) {
            float den = fmaf(na[i], nb[j], 0.01f);
            d[i][j] = 1.0f - (dv[j] * INV256) * __frcp_rn(den);
        }
    }

    float r = otam_dp<false>(d) + otam_dp<true>(d);
    int c = labels[sp];
    atomicAdd(&out[q * NCLS + c], -r * g_invcnt[c]);
}

// -------- launcher --------
extern "C" void kernel_launch(void* const* d_in, const int* in_sizes, int n_in,
                              void* d_out, int out_size) {
    const float* tf = (const float*)d_in[0];      // [2048, 8, 2048]
    const float* sf = (const float*)d_in[1];      // [100, 8, 2048]
    const int* labels = (const int*)d_in[2];      // [100]
    float* out = (float*)d_out;                   // [1, 2048, 20]

    cudaFuncSetAttribute(k_gemm, cudaFuncAttributeMaxDynamicSharedMemorySize, SM_BYTES);

    k_zero<<<(out_size + 255) / 256, 256>>>(out, out_size, labels);
    k_conv<<<(MROWS + NPAD) / 2, 256>>>(tf, sf);
    dim3 ggrid(NPAD / BN, MROWS / BM);
    k_gemm<<<ggrid, 256, SM_BYTES>>>();
    k_otam<<<(QN * SPN + 127) / 128, 128>>>(labels, out);
}